// round 1
// baseline (speedup 1.0000x reference)
#include <cuda_runtime.h>
#include <math.h>

// ---------------- problem constants (fixed shapes in the dataset) -----------
#define Bc   64
#define Sc   128
#define Dc   2048
#define Pc   118
#define Cc   2
#define Vc   512

#define D4c  (Dc/4)            // 512
#define PCc  (Pc*Cc)           // 236
#define PC4c (PCc/4)           // 59
#define V4c  (Vc/4)            // 128

#define R1c  (Bc*Sc*D4c)       // 4,194,304  recon vec4s
#define R2c  (Bc*Sc*PC4c)      //   483,328  pts vec4s
#define R3c  (Bc*Sc*V4c)       // 1,048,576  kld vec4s
#define R4c  (Bc*PC4c)         //     3,776  best vec4s
#define TOTc (R1c+R2c+R3c+R4c)

#define NBLK 1184
#define NTHR 256

#define EPSf  1e-20f
#define LOGGf (-6.23832462503951f)   // log(1/512)

// per-block partial sums: [block][6] = recon, disk, lm, kld, best, bestlm
__device__ float g_part[NBLK][6];

__device__ __forceinline__ bool is_mark(int p) {
    return (p == 0) | (p == 29) | (p == 88) | (p == 117);
}

__global__ __launch_bounds__(NTHR) void loss_main(
    const float4* __restrict__ zs,
    const float4* __restrict__ rzs,
    const float4* __restrict__ pts,
    const float4* __restrict__ pts_gt,
    const float4* __restrict__ qy,
    const float4* __restrict__ best,
    const float4* __restrict__ best_gt,
    const void*   __restrict__ mapping)
{
    // ---- detect mapping dtype width (int64 vs canonicalized int32) ----
    __shared__ int s_is64;
    if (threadIdx.x == 0) {
        const int* mi = (const int*)mapping;
        int nz = 0;
        #pragma unroll
        for (int i = 0; i < 64; i++) nz |= mi[2 * i + 1];
        s_is64 = (nz == 0);
    }
    __syncthreads();
    const int is64 = s_is64;
    const int*       m32 = (const int*)mapping;
    const long long* m64 = (const long long*)mapping;

    float recon = 0.f, disk = 0.f, lm = 0.f, kld = 0.f, bsum = 0.f, blm = 0.f;

    const int stride = gridDim.x * blockDim.x;
    for (int idx = blockIdx.x * blockDim.x + threadIdx.x; idx < TOTc; idx += stride) {
        if (idx < R1c) {
            // ---- recon: mse( rzs[b, mapping[b,s], :], zs[b,s,:] ) ----
            int row = idx >> 9;           // / D4c (512)
            int d4  = idx & (D4c - 1);
            int b   = row >> 7;           // / Sc (128)
            int m   = is64 ? (int)m64[row] : m32[row];
            float4 a = zs[idx];
            float4 r = rzs[((b << 7) + m) * D4c + d4];
            float dx = a.x - r.x, dy = a.y - r.y, dz = a.z - r.z, dw = a.w - r.w;
            recon += dx * dx + dy * dy + dz * dz + dw * dw;
        } else if (idx < R1c + R2c) {
            // ---- pts: gathered mse + landmark mse ----
            int e   = idx - R1c;
            int row = e / PC4c;
            int j4  = e - row * PC4c;
            int b   = row >> 7;
            int m   = is64 ? (int)m64[row] : m32[row];
            float4 g = pts_gt[e];
            float4 x = pts[((b << 7) + m) * PC4c + j4];
            int p0 = j4 * 2, p1 = p0 + 1;  // C=2: components (x,y)->p0, (z,w)->p1
            float dx = x.x - g.x, dy = x.y - g.y, dz = x.z - g.z, dw = x.w - g.w;
            float s01 = dx * dx + dy * dy;
            float s23 = dz * dz + dw * dw;
            disk += s01 + s23;
            if (is_mark(p0)) lm += s01;
            if (is_mark(p1)) lm += s23;
        } else if (idx < R1c + R2c + R3c) {
            // ---- KL vs uniform ----
            int e = idx - (R1c + R2c);
            float4 q = qy[e];
            kld += q.x * (logf(q.x + EPSf) - LOGGf);
            kld += q.y * (logf(q.y + EPSf) - LOGGf);
            kld += q.z * (logf(q.z + EPSf) - LOGGf);
            kld += q.w * (logf(q.w + EPSf) - LOGGf);
        } else {
            // ---- best: mse + landmark mse ----
            int e  = idx - (R1c + R2c + R3c);
            int rb = e / PC4c;
            int j4 = e - rb * PC4c;
            float4 a = best[e];
            float4 g = best_gt[e];
            int p0 = j4 * 2, p1 = p0 + 1;
            float dx = a.x - g.x, dy = a.y - g.y, dz = a.z - g.z, dw = a.w - g.w;
            float s01 = dx * dx + dy * dy;
            float s23 = dz * dz + dw * dw;
            bsum += s01 + s23;
            if (is_mark(p0)) blm += s01;
            if (is_mark(p1)) blm += s23;
        }
    }

    // ---- block reduction: warp shfl, then thread 0 combines 8 warps ----
    #pragma unroll
    for (int o = 16; o > 0; o >>= 1) {
        recon += __shfl_down_sync(0xffffffffu, recon, o);
        disk  += __shfl_down_sync(0xffffffffu, disk,  o);
        lm    += __shfl_down_sync(0xffffffffu, lm,    o);
        kld   += __shfl_down_sync(0xffffffffu, kld,   o);
        bsum  += __shfl_down_sync(0xffffffffu, bsum,  o);
        blm   += __shfl_down_sync(0xffffffffu, blm,   o);
    }
    __shared__ float sw[NTHR / 32][6];
    int lane = threadIdx.x & 31, w = threadIdx.x >> 5;
    if (lane == 0) {
        sw[w][0] = recon; sw[w][1] = disk; sw[w][2] = lm;
        sw[w][3] = kld;   sw[w][4] = bsum; sw[w][5] = blm;
    }
    __syncthreads();
    if (threadIdx.x == 0) {
        float t[6] = {0, 0, 0, 0, 0, 0};
        #pragma unroll
        for (int i = 0; i < NTHR / 32; i++)
            #pragma unroll
            for (int k = 0; k < 6; k++) t[k] += sw[i][k];
        #pragma unroll
        for (int k = 0; k < 6; k++) g_part[blockIdx.x][k] = t[k];
    }
}

__global__ void loss_finalize(float* __restrict__ out)
{
    int tid  = threadIdx.x;
    int comp = tid >> 5;      // one warp per component, comps 0..5 active
    int lane = tid & 31;
    __shared__ float tot[8];
    if (comp < 6) {
        float s = 0.f;
        for (int i = lane; i < NBLK; i += 32) s += g_part[i][comp];
        #pragma unroll
        for (int o = 16; o > 0; o >>= 1) s += __shfl_down_sync(0xffffffffu, s, o);
        if (lane == 0) tot[comp] = s;
    }
    __syncthreads();
    if (tid == 0) {
        float recon = tot[0] / (float)(Bc * Sc * Dc);          // 16,777,216
        float disk  = tot[1] / (float)(Bc * Sc * Pc * Cc);     //  1,933,312
        float lmk   = tot[2] / (float)(Bc * Sc * 4 * Cc);      //     65,536
        float kld   = tot[3] / (float)(Bc * Sc);               //      8,192
        float bs    = tot[4] / (float)(Bc * Pc * Cc);          //     15,104
        float blm   = tot[5] / (float)(Bc * 4 * Cc);           //        512
        // total = BETA*kld + GAMMA*recon + (disk + ALPHA*lm) + (best + ALPHA*best_lm)
        out[0] = 0.1f * kld + recon + (disk + 10.f * lmk) + (bs + 10.f * blm);
    }
}

extern "C" void kernel_launch(void* const* d_in, const int* in_sizes, int n_in,
                              void* d_out, int out_size)
{
    const float4* zs      = (const float4*)d_in[0];
    const float4* rzs     = (const float4*)d_in[1];
    const float4* pts     = (const float4*)d_in[2];
    const float4* pts_gt  = (const float4*)d_in[3];
    const float4* qy      = (const float4*)d_in[4];
    // d_in[5] = logits : unused by the loss
    const float4* best    = (const float4*)d_in[6];
    const float4* best_gt = (const float4*)d_in[7];
    const void*   mapping = (const void*)d_in[8];
    // d_in[9] = vector_dims scalar : compile-time constant (512)

    loss_main<<<NBLK, NTHR>>>(zs, rzs, pts, pts_gt, qy, best, best_gt, mapping);
    loss_finalize<<<1, 256>>>((float*)d_out);
}